// round 4
// baseline (speedup 1.0000x reference)
#include <cuda_runtime.h>
#include <cstdint>

#define NVOX 50000
#define PPV  32
#define CIN  4
#define HID  64
#define OUT  128
#define EPSV 1e-5f

// Folded weights (BN baked into linear layers). Scratch via __device__ globals.
__device__ __align__(16) float g_W1f[CIN * HID];
__device__ __align__(16) float g_b1f[HID];
__device__ __align__(16) float g_W2f[HID * HID];
__device__ __align__(16) float g_b2f[HID];
__device__ int g_npts_is64;

// ---------------------------------------------------------------------------
// Probe: detect int32 vs int64 layout of voxel_num_points.
// Values are in [1,32]. If int64 (LE), word[1] is the high word of element 0
// == 0. If int32, word[1] == npts[1] in [1,32] != 0.
// ---------------------------------------------------------------------------
__global__ void probe_npts_kernel(const int* __restrict__ p32) {
    g_npts_is64 = (p32[1] == 0) ? 1 : 0;
}

// ---------------------------------------------------------------------------
// Prep: fold BN into the two linear layers.  y = ((xW+b)-m)*rsqrt(v+e)*g+be
//   => W' = W * s,  b' = (b-m)*s + be,   s = g*rsqrt(v+e)
// ---------------------------------------------------------------------------
__global__ void fold_bn_kernel(const float* __restrict__ W1, const float* __restrict__ b1,
                               const float* __restrict__ g1, const float* __restrict__ be1,
                               const float* __restrict__ m1, const float* __restrict__ v1,
                               const float* __restrict__ W2, const float* __restrict__ b2,
                               const float* __restrict__ g2, const float* __restrict__ be2,
                               const float* __restrict__ m2, const float* __restrict__ v2) {
    int h = threadIdx.x;
    if (h >= HID) return;
    float s1 = g1[h] * rsqrtf(v1[h] + EPSV);
    g_b1f[h] = (b1[h] - m1[h]) * s1 + be1[h];
#pragma unroll
    for (int c = 0; c < CIN; ++c) g_W1f[c * HID + h] = W1[c * HID + h] * s1;

    float s2 = g2[h] * rsqrtf(v2[h] + EPSV);
    g_b2f[h] = (b2[h] - m2[h]) * s2 + be2[h];
#pragma unroll
    for (int k = 0; k < HID; ++k) g_W2f[k * HID + h] = W2[k * HID + h] * s2;
}

// ---------------------------------------------------------------------------
// Packed fp32x2 FMA (Blackwell FFMA2) — 2x fp32 FMA throughput vs scalar FFMA.
// ---------------------------------------------------------------------------
union F2 {
    float2 f;
    unsigned long long u;
};

__device__ __forceinline__ void fma2(F2& d, const F2 a, const F2 b) {
    asm("fma.rn.f32x2 %0, %1, %2, %3;" : "=l"(d.u) : "l"(a.u), "l"(b.u), "l"(d.u));
}

__device__ __forceinline__ F2 dup2(float x) {
    F2 r; r.f.x = x; r.f.y = x; return r;
}

// ---------------------------------------------------------------------------
// Main kernel: 1 warp per voxel, 1 lane per point.
//   layer1: 4->64 from global (L1-resident, broadcast)
//   layer2: 64->64 from SMEM (16KB)
//   layer3: 64->128 from SMEM (32KB), 4 chunks of 32 channels
//   masked max over lanes via shfl butterfly, lane0 STG.128 epilogue.
// ---------------------------------------------------------------------------
__global__ __launch_bounds__(256, 1)
void vfe_kernel(const float* __restrict__ vf,         // (NVOX, PPV, CIN)
                const void* __restrict__ npts_raw,    // (NVOX,) int32 or int64
                const float* __restrict__ W3,         // (HID, OUT)
                const float* __restrict__ b3,         // (OUT,)
                float* __restrict__ out)              // (NVOX, OUT)
{
    __shared__ __align__(16) float sW2[HID * HID];  // 16KB
    __shared__ __align__(16) float sW3[HID * OUT];  // 32KB  (total = 48KB exactly)

    // cooperative stage of weights
    {
        const float4* s2 = (const float4*)g_W2f;
        float4* d2 = (float4*)sW2;
        for (int i = threadIdx.x; i < HID * HID / 4; i += 256) d2[i] = s2[i];
        const float4* s3 = (const float4*)W3;
        float4* d3 = (float4*)sW3;
        for (int i = threadIdx.x; i < HID * OUT / 4; i += 256) d3[i] = s3[i];
    }
    __syncthreads();

    const int warp = (blockIdx.x * blockDim.x + threadIdx.x) >> 5;  // == voxel id
    const int lane = threadIdx.x & 31;
    if (warp >= NVOX) return;

    // dtype-agnostic point count (uniform branch; values fit in int32 low word)
    int n;
    if (g_npts_is64) n = (int)((const long long*)npts_raw)[warp];
    else             n = ((const int*)npts_raw)[warp];
    const bool valid = lane < n;

    const float4 x = ((const float4*)vf)[warp * PPV + lane];

    // ---- layer 1: 4 -> 64, relu(bn folded) ----
    float h1[HID];
#pragma unroll
    for (int h4 = 0; h4 < HID / 4; ++h4) {
        float4 w0 = ((const float4*)g_W1f)[0 * 16 + h4];
        float4 w1 = ((const float4*)g_W1f)[1 * 16 + h4];
        float4 w2 = ((const float4*)g_W1f)[2 * 16 + h4];
        float4 w3 = ((const float4*)g_W1f)[3 * 16 + h4];
        float4 bb = ((const float4*)g_b1f)[h4];
        h1[4 * h4 + 0] = fmaxf(0.f, bb.x + x.x * w0.x + x.y * w1.x + x.z * w2.x + x.w * w3.x);
        h1[4 * h4 + 1] = fmaxf(0.f, bb.y + x.x * w0.y + x.y * w1.y + x.z * w2.y + x.w * w3.y);
        h1[4 * h4 + 2] = fmaxf(0.f, bb.z + x.x * w0.z + x.y * w1.z + x.z * w2.z + x.w * w3.z);
        h1[4 * h4 + 3] = fmaxf(0.f, bb.w + x.x * w0.w + x.y * w1.w + x.z * w2.w + x.w * w3.w);
    }

    // ---- layer 2: 64 -> 64, packed FMA, relu(bn folded) ----
    F2 h2[HID / 2];
    // FIX (R3): bias init must cover ALL 32 F2 slots -> 16 float4 iterations
    // (previous HID/8=8 left h2[16..31] uninitialized => rel_err 0.17)
#pragma unroll
    for (int i = 0; i < HID / 4; ++i) {
        float4 bb = ((const float4*)g_b2f)[i];
        h2[2 * i + 0].f = make_float2(bb.x, bb.y);
        h2[2 * i + 1].f = make_float2(bb.z, bb.w);
    }
#pragma unroll
    for (int k = 0; k < HID; ++k) {
        const F2 a = dup2(h1[k]);
        const float4* row = (const float4*)(sW2 + k * HID);
#pragma unroll
        for (int j = 0; j < HID / 4; ++j) {
            float4 w = row[j];
            F2 b0; b0.f = make_float2(w.x, w.y);
            F2 b1v; b1v.f = make_float2(w.z, w.w);
            fma2(h2[2 * j + 0], a, b0);
            fma2(h2[2 * j + 1], a, b1v);
        }
    }
    // relu into h1 (reuse registers; h1 is dead)
#pragma unroll
    for (int i = 0; i < HID / 2; ++i) {
        h1[2 * i + 0] = fmaxf(0.f, h2[i].f.x);
        h1[2 * i + 1] = fmaxf(0.f, h2[i].f.y);
    }

    const float NEG_INF = __int_as_float(0xff800000);

    // ---- layer 3: 64 -> 128 in 4 chunks of 32 channels + masked warp max ----
#pragma unroll
    for (int chunk = 0; chunk < 4; ++chunk) {
        const int base = chunk * 32;
        F2 a3[16];
#pragma unroll
        for (int i = 0; i < 8; ++i) {
            float4 bb = ((const float4*)b3)[chunk * 8 + i];
            a3[2 * i + 0].f = make_float2(bb.x, bb.y);
            a3[2 * i + 1].f = make_float2(bb.z, bb.w);
        }
#pragma unroll
        for (int k = 0; k < HID; ++k) {
            const F2 a = dup2(h1[k]);
            const float4* row = (const float4*)(sW3 + k * OUT + base);
#pragma unroll
            for (int j = 0; j < 8; ++j) {
                float4 w = row[j];
                F2 b0; b0.f = make_float2(w.x, w.y);
                F2 b1v; b1v.f = make_float2(w.z, w.w);
                fma2(a3[2 * j + 0], a, b0);
                fma2(a3[2 * j + 1], a, b1v);
            }
        }
        // mask out invalid points
#pragma unroll
        for (int i = 0; i < 16; ++i) {
            if (!valid) { a3[i].f.x = NEG_INF; a3[i].f.y = NEG_INF; }
        }
        // butterfly max across the 32 lanes (points)
#pragma unroll
        for (int d = 16; d >= 1; d >>= 1) {
#pragma unroll
            for (int i = 0; i < 16; ++i) {
                F2 t; t.u = __shfl_xor_sync(0xffffffffu, a3[i].u, d);
                a3[i].f.x = fmaxf(a3[i].f.x, t.f.x);
                a3[i].f.y = fmaxf(a3[i].f.y, t.f.y);
            }
        }
        if (lane == 0) {
            float4* dst = (float4*)(out + (size_t)warp * OUT + base);
#pragma unroll
            for (int j = 0; j < 8; ++j) {
                dst[j] = make_float4(a3[2 * j].f.x, a3[2 * j].f.y,
                                     a3[2 * j + 1].f.x, a3[2 * j + 1].f.y);
            }
        }
    }
}

// ---------------------------------------------------------------------------
// Launch
// ---------------------------------------------------------------------------
extern "C" void kernel_launch(void* const* d_in, const int* in_sizes, int n_in,
                              void* d_out, int out_size) {
    const float* vf  = (const float*)d_in[0];   // voxel_features
    const void*  np  = d_in[1];                 // voxel_num_points (int32 or int64)
    const float* W1  = (const float*)d_in[2];
    const float* b1  = (const float*)d_in[3];
    const float* g1  = (const float*)d_in[4];
    const float* be1 = (const float*)d_in[5];
    const float* m1  = (const float*)d_in[6];
    const float* v1  = (const float*)d_in[7];
    const float* W2  = (const float*)d_in[8];
    const float* b2  = (const float*)d_in[9];
    const float* g2  = (const float*)d_in[10];
    const float* be2 = (const float*)d_in[11];
    const float* m2  = (const float*)d_in[12];
    const float* v2  = (const float*)d_in[13];
    const float* W3  = (const float*)d_in[14];
    const float* b3  = (const float*)d_in[15];
    float* out = (float*)d_out;

    probe_npts_kernel<<<1, 1>>>((const int*)np);
    fold_bn_kernel<<<1, HID>>>(W1, b1, g1, be1, m1, v1, W2, b2, g2, be2, m2, v2);

    const int warps_per_block = 8;
    const int blocks = NVOX / warps_per_block;  // 6250, exact
    vfe_kernel<<<blocks, warps_per_block * 32>>>(vf, np, W3, b3, out);
}

// round 12
// speedup vs baseline: 6.1749x; 6.1749x over previous
#include <cuda_runtime.h>
#include <cuda_bf16.h>
#include <cstdint>

#define NVOX 50000
#define PPV  32
#define CIN  4
#define HID  64
#define OUT  128
#define EPSV 1e-5f

#define TILE_M 128          // rows per CTA = 4 voxels
#define NTILES (NVOX / 4)   // 12500

// ---------------- dynamic SMEM layout (bytes) ----------------
#define OFF_AH   0u                    // A hi  (128 x 64 bf16) 16KB
#define OFF_AL   16384u                // A lo                   16KB
#define OFF_B2H  32768u                // W2^T hi (64 x 64 bf16)  8KB
#define OFF_B2L  40960u                //                         8KB
#define OFF_B3H  49152u                // W3^T hi (128 x 64 bf16)16KB
#define OFF_B3L  65536u                //                        16KB
#define SMEM_TOTAL 81920u              // 80KB -> 2 CTAs/SM

__device__ __forceinline__ uint32_t sw128(uint32_t x) { return x ^ ((x >> 3) & 0x70); }

// ---------------- device globals (prep outputs) ----------------
__device__ __align__(16) float g_W1f[CIN * HID];
__device__ __align__(16) float g_b1f[HID];
__device__ __align__(16) float g_b2f[HID];
__device__ __align__(16) unsigned short g_B2h[HID * HID];    // [n][k] bf16, swizzled
__device__ __align__(16) unsigned short g_B2l[HID * HID];
__device__ __align__(16) unsigned short g_B3h[OUT * HID];
__device__ __align__(16) unsigned short g_B3l[OUT * HID];
__device__ int g_npts_is64;

// ---------------- PTX helpers (all baseline sm_80+, no 'a' gate) ----------------
__device__ __forceinline__ uint32_t smem_u32(const void* p) {
    uint32_t a;
    asm("{ .reg .u64 t; cvta.to.shared.u64 t, %1; cvt.u32.u64 %0, t; }" : "=r"(a) : "l"(p));
    return a;
}

__device__ __forceinline__ void ldsm_x4(uint32_t* r, uint32_t addr) {
    asm volatile("ldmatrix.sync.aligned.m8n8.x4.shared.b16 {%0,%1,%2,%3}, [%4];"
                 : "=r"(r[0]), "=r"(r[1]), "=r"(r[2]), "=r"(r[3]) : "r"(addr));
}
__device__ __forceinline__ void ldsm_x2(uint32_t* r, uint32_t addr) {
    asm volatile("ldmatrix.sync.aligned.m8n8.x2.shared.b16 {%0,%1}, [%2];"
                 : "=r"(r[0]), "=r"(r[1]) : "r"(addr));
}
__device__ __forceinline__ void mma_bf16(float* c, const uint32_t* a, const uint32_t* b) {
    asm volatile("mma.sync.aligned.m16n8k16.row.col.f32.bf16.bf16.f32 "
                 "{%0,%1,%2,%3}, {%4,%5,%6,%7}, {%8,%9}, {%0,%1,%2,%3};"
                 : "+f"(c[0]), "+f"(c[1]), "+f"(c[2]), "+f"(c[3])
                 : "r"(a[0]), "r"(a[1]), "r"(a[2]), "r"(a[3]), "r"(b[0]), "r"(b[1]));
}

// pack two f32 -> bf16x2 word (v0 -> low half)
__device__ __forceinline__ uint32_t pack2(float v0, float v1) {
    uint32_t r;
    asm("cvt.rn.bf16x2.f32 %0, %1, %2;" : "=r"(r) : "f"(v1), "f"(v0));
    return r;
}

// relu(c+b) -> bf16 hi + residual lo, packed
__device__ __forceinline__ void cvt_pair(float c0, float c1, float bx, float by,
                                         uint32_t& hi, uint32_t& lo) {
    float v0 = fmaxf(0.f, c0 + bx);
    float v1 = fmaxf(0.f, c1 + by);
    hi = pack2(v0, v1);
    float r0 = v0 - __uint_as_float(hi << 16);
    float r1 = v1 - __uint_as_float(hi & 0xFFFF0000u);
    lo = pack2(r0, r1);
}

// split v[64] into bf16 hi/lo and store swizzled 128B rows into A tiles
__device__ __forceinline__ void split_store_row(char* sm, int row, const float* v) {
    uint32_t ah[32], al[32];
#pragma unroll
    for (int p = 0; p < 32; ++p) {
        float v0 = v[2 * p], v1 = v[2 * p + 1];
        uint32_t wh = pack2(v0, v1);
        float r0 = v0 - __uint_as_float(wh << 16);
        float r1 = v1 - __uint_as_float(wh & 0xFFFF0000u);
        ah[p] = wh;
        al[p] = pack2(r0, r1);
    }
#pragma unroll
    for (int i = 0; i < 8; ++i) {
        uint32_t off = sw128((uint32_t)(row * 128 + i * 16));
        *(uint4*)(sm + OFF_AH + off) = make_uint4(ah[4 * i], ah[4 * i + 1], ah[4 * i + 2], ah[4 * i + 3]);
        *(uint4*)(sm + OFF_AL + off) = make_uint4(al[4 * i], al[4 * i + 1], al[4 * i + 2], al[4 * i + 3]);
    }
}

// ---------------------------------------------------------------------------
// Prep kernel: BN fold, weight transpose + bf16 split + swizzle, dtype probe.
// ---------------------------------------------------------------------------
__global__ void prep_kernel(const float* __restrict__ W1, const float* __restrict__ b1,
                            const float* __restrict__ g1, const float* __restrict__ be1,
                            const float* __restrict__ m1, const float* __restrict__ v1,
                            const float* __restrict__ W2, const float* __restrict__ b2,
                            const float* __restrict__ g2, const float* __restrict__ be2,
                            const float* __restrict__ m2, const float* __restrict__ v2,
                            const float* __restrict__ W3,
                            const int* __restrict__ np32) {
    __shared__ float s2sh[HID];
    int t = threadIdx.x;
    if (t < HID) {
        float s1 = g1[t] * rsqrtf(v1[t] + EPSV);
        g_b1f[t] = (b1[t] - m1[t]) * s1 + be1[t];
#pragma unroll
        for (int c = 0; c < CIN; ++c) g_W1f[c * HID + t] = W1[c * HID + t] * s1;
        float s2 = g2[t] * rsqrtf(v2[t] + EPSV);
        g_b2f[t] = (b2[t] - m2[t]) * s2 + be2[t];
        s2sh[t] = s2;
    }
    if (t == 0) g_npts_is64 = (np32[1] == 0) ? 1 : 0;
    __syncthreads();

    // B2[n][k] = W2[k][n] * s2[n], swizzled, split hi/lo
    for (int i = t; i < HID * HID; i += blockDim.x) {
        int n = i / HID, k = i % HID;
        float v = W2[k * HID + n] * s2sh[n];
        __nv_bfloat16 bh = __float2bfloat16(v);
        float rl = v - __bfloat162float(bh);
        __nv_bfloat16 bl = __float2bfloat16(rl);
        uint32_t idx = sw128((uint32_t)(n * 128 + k * 2)) >> 1;
        g_B2h[idx] = __bfloat16_as_ushort(bh);
        g_B2l[idx] = __bfloat16_as_ushort(bl);
    }
    // B3[n][k] = W3[k][n], swizzled, split hi/lo
    for (int i = t; i < OUT * HID; i += blockDim.x) {
        int n = i / HID, k = i % HID;
        float v = W3[k * OUT + n];
        __nv_bfloat16 bh = __float2bfloat16(v);
        float rl = v - __bfloat162float(bh);
        __nv_bfloat16 bl = __float2bfloat16(rl);
        uint32_t idx = sw128((uint32_t)(n * 128 + k * 2)) >> 1;
        g_B3h[idx] = __bfloat16_as_ushort(bh);
        g_B3l[idx] = __bfloat16_as_ushort(bl);
    }
}

// ---------------------------------------------------------------------------
// Main kernel: 1 CTA = 128 rows = 4 voxels. mma.sync bf16x3 for layers 2+3.
// Warp w owns rows 32w..32w+31 == voxel blockIdx.x*4 + w.
// ---------------------------------------------------------------------------
__global__ void __launch_bounds__(128, 2)
vfe_hmma_kernel(const float* __restrict__ vf,
                const void* __restrict__ npts_raw,
                const float* __restrict__ b3,
                float* __restrict__ out) {
    extern __shared__ __align__(1024) char smem[];
    const uint32_t sbase = smem_u32(smem);
    const int tid = threadIdx.x;
    const int wid = tid >> 5;
    const int lane = tid & 31;

    // ---- stage B tiles (pre-swizzled; linear copy) ----
    {
        uint4* d; const uint4* s;
        d = (uint4*)(smem + OFF_B2H); s = (const uint4*)g_B2h;
        for (int i = tid; i < 512; i += 128) d[i] = s[i];
        d = (uint4*)(smem + OFF_B2L); s = (const uint4*)g_B2l;
        for (int i = tid; i < 512; i += 128) d[i] = s[i];
        d = (uint4*)(smem + OFF_B3H); s = (const uint4*)g_B3h;
        for (int i = tid; i < 1024; i += 128) d[i] = s[i];
        d = (uint4*)(smem + OFF_B3L); s = (const uint4*)g_B3l;
        for (int i = tid; i < 1024; i += 128) d[i] = s[i];
    }

    // ---- layer 1 (4 -> 64) on CUDA cores, one row per thread ----
    {
        const int gr = blockIdx.x * TILE_M + tid;
        const float4 x = ((const float4*)vf)[gr];
        float h1[HID];
#pragma unroll
        for (int h4 = 0; h4 < HID / 4; ++h4) {
            float4 w0 = ((const float4*)g_W1f)[0 * 16 + h4];
            float4 w1 = ((const float4*)g_W1f)[1 * 16 + h4];
            float4 w2 = ((const float4*)g_W1f)[2 * 16 + h4];
            float4 w3 = ((const float4*)g_W1f)[3 * 16 + h4];
            float4 bb = ((const float4*)g_b1f)[h4];
            h1[4 * h4 + 0] = fmaxf(0.f, bb.x + x.x * w0.x + x.y * w1.x + x.z * w2.x + x.w * w3.x);
            h1[4 * h4 + 1] = fmaxf(0.f, bb.y + x.x * w0.y + x.y * w1.y + x.z * w2.y + x.w * w3.y);
            h1[4 * h4 + 2] = fmaxf(0.f, bb.z + x.x * w0.z + x.y * w1.z + x.z * w2.z + x.w * w3.z);
            h1[4 * h4 + 3] = fmaxf(0.f, bb.w + x.x * w0.w + x.y * w1.w + x.z * w2.w + x.w * w3.w);
        }
        split_store_row(smem, tid, h1);
    }
    __syncthreads();   // B tiles + all A rows visible

    // ---- fragment address precompute ----
    // swizzle XOR for this lane's rows (row%8 == lane&7 for both A and B patterns)
    const uint32_t swz = (uint32_t)(lane & 7) << 4;
    // A (x4): lane -> row base+(l&15), col 16B-sel (l&16)
    const uint32_t aRowSel = (uint32_t)(lane & 15);
    const uint32_t aColSel = (uint32_t)(lane & 16);
    // B (x2): lane -> row (l&7), col 16B-sel ((l&8)?16:0)
    const uint32_t bRowSel = (uint32_t)(lane & 7);
    const uint32_t bColSel = (uint32_t)((lane & 8) << 1);

    const int t4 = lane & 3;          // fragment col-group
    // per-warp A row bases (m-tiles): rows 32*wid + 16*mt
    uint32_t aBase[2];
#pragma unroll
    for (int mt = 0; mt < 2; ++mt)
        aBase[mt] = sbase + OFF_AH + (32u * wid + 16u * mt + aRowSel) * 128u;

    // ---- layer 2: acc2[mt][nt][4] = A(128x64) @ B2^T ----
    float acc2[2][8][4];
#pragma unroll
    for (int mt = 0; mt < 2; ++mt)
#pragma unroll
        for (int nt = 0; nt < 8; ++nt)
#pragma unroll
            for (int q = 0; q < 4; ++q) acc2[mt][nt][q] = 0.f;

#pragma unroll
    for (int pass = 0; pass < 3; ++pass) {
        const uint32_t aOff = (pass == 2) ? (OFF_AL - OFF_AH) : 0u;
        const uint32_t bTile = sbase + ((pass == 1) ? OFF_B2L : OFF_B2H);
#pragma unroll
        for (int ks = 0; ks < 4; ++ks) {
            const uint32_t colA = (32u * ks + aColSel) ^ swz;
            const uint32_t colB = (32u * ks + bColSel) ^ swz;
            uint32_t af[2][4];
#pragma unroll
            for (int mt = 0; mt < 2; ++mt) ldsm_x4(af[mt], aBase[mt] + aOff + colA);
            uint32_t bf[8][2];
#pragma unroll
            for (int nt = 0; nt < 8; ++nt)
                ldsm_x2(bf[nt], bTile + (8u * nt + bRowSel) * 128u + colB);
#pragma unroll
            for (int mt = 0; mt < 2; ++mt)
#pragma unroll
                for (int nt = 0; nt < 8; ++nt) mma_bf16(acc2[mt][nt], af[mt], bf[nt]);
        }
    }

    // ---- convert: relu(acc2+b2) -> layer-3 A fragments in registers ----
    // acc(m16n16 from n-tile pair) layout == a-frag(m16k16) layout.
    uint32_t ahi[2][4][4], alo[2][4][4];   // [mt][ks][reg]
#pragma unroll
    for (int ks = 0; ks < 4; ++ks) {
        const int nt0 = 2 * ks, nt1 = 2 * ks + 1;
        const float2 bb0 = *(const float2*)(g_b2f + 8 * nt0 + 2 * t4);
        const float2 bb1 = *(const float2*)(g_b2f + 8 * nt1 + 2 * t4);
#pragma unroll
        for (int mt = 0; mt < 2; ++mt) {
            cvt_pair(acc2[mt][nt0][0], acc2[mt][nt0][1], bb0.x, bb0.y, ahi[mt][ks][0], alo[mt][ks][0]);
            cvt_pair(acc2[mt][nt0][2], acc2[mt][nt0][3], bb0.x, bb0.y, ahi[mt][ks][1], alo[mt][ks][1]);
            cvt_pair(acc2[mt][nt1][0], acc2[mt][nt1][1], bb1.x, bb1.y, ahi[mt][ks][2], alo[mt][ks][2]);
            cvt_pair(acc2[mt][nt1][2], acc2[mt][nt1][3], bb1.x, bb1.y, ahi[mt][ks][3], alo[mt][ks][3]);
        }
    }

    // ---- voxel point count (for masked max) ----
    const int voxel = blockIdx.x * 4 + wid;
    int n;
    if (g_npts_is64) n = (int)((const long long*)npts_raw)[voxel];
    else             n = ((const int*)npts_raw)[voxel];
    const int g = lane >> 2;
    const bool v0r = (g      < n);
    const bool v1r = (g +  8 < n);
    const bool v2r = (g + 16 < n);
    const bool v3r = (g + 24 < n);
    const float NEG_INF = __int_as_float(0xff800000);

    // ---- layer 3 in two 64-col halves + fused epilogue ----
#pragma unroll
    for (int hh = 0; hh < 2; ++hh) {
        float acc3[2][8][4];
#pragma unroll
        for (int mt = 0; mt < 2; ++mt)
#pragma unroll
            for (int nt = 0; nt < 8; ++nt)
#pragma unroll
                for (int q = 0; q < 4; ++q) acc3[mt][nt][q] = 0.f;

#pragma unroll
        for (int pass = 0; pass < 3; ++pass) {
            const uint32_t bTile = sbase + ((pass == 1) ? OFF_B3L : OFF_B3H) + (uint32_t)hh * 64u * 128u;
#pragma unroll
            for (int ks = 0; ks < 4; ++ks) {
                const uint32_t colB = (32u * ks + bColSel) ^ swz;
                uint32_t bf[8][2];
#pragma unroll
                for (int nt = 0; nt < 8; ++nt)
                    ldsm_x2(bf[nt], bTile + (8u * nt + bRowSel) * 128u + colB);
#pragma unroll
                for (int mt = 0; mt < 2; ++mt) {
                    const uint32_t* a = (pass == 2) ? alo[mt][ks] : ahi[mt][ks];
#pragma unroll
                    for (int nt = 0; nt < 8; ++nt) mma_bf16(acc3[mt][nt], a, bf[nt]);
                }
            }
        }

        // epilogue: masked max over 32 rows (points), +b3 after max
#pragma unroll
        for (int nt = 0; nt < 8; ++nt) {
            float m0 = v0r ? acc3[0][nt][0] : NEG_INF;
            float m1 = v0r ? acc3[0][nt][1] : NEG_INF;
            m0 = fmaxf(m0, v1r ? acc3[0][nt][2] : NEG_INF);
            m1 = fmaxf(m1, v1r ? acc3[0][nt][3] : NEG_INF);
            m0 = fmaxf(m0, v2r ? acc3[1][nt][0] : NEG_INF);
            m1 = fmaxf(m1, v2r ? acc3[1][nt][1] : NEG_INF);
            m0 = fmaxf(m0, v3r ? acc3[1][nt][2] : NEG_INF);
            m1 = fmaxf(m1, v3r ? acc3[1][nt][3] : NEG_INF);
#pragma unroll
            for (int d = 4; d <= 16; d <<= 1) {
                m0 = fmaxf(m0, __shfl_xor_sync(0xffffffffu, m0, d));
                m1 = fmaxf(m1, __shfl_xor_sync(0xffffffffu, m1, d));
            }
            if (lane < 4) {
                const int col = hh * 64 + nt * 8 + 2 * lane;
                const float2 bb = *(const float2*)(b3 + col);
                *(float2*)(out + (size_t)voxel * OUT + col) = make_float2(m0 + bb.x, m1 + bb.y);
            }
        }
    }
}

// ---------------------------------------------------------------------------
// Launch
// ---------------------------------------------------------------------------
extern "C" void kernel_launch(void* const* d_in, const int* in_sizes, int n_in,
                              void* d_out, int out_size) {
    const float* vf  = (const float*)d_in[0];
    const void*  np  = d_in[1];
    const float* W1  = (const float*)d_in[2];
    const float* b1  = (const float*)d_in[3];
    const float* g1  = (const float*)d_in[4];
    const float* be1 = (const float*)d_in[5];
    const float* m1  = (const float*)d_in[6];
    const float* v1  = (const float*)d_in[7];
    const float* W2  = (const float*)d_in[8];
    const float* b2  = (const float*)d_in[9];
    const float* g2  = (const float*)d_in[10];
    const float* be2 = (const float*)d_in[11];
    const float* m2  = (const float*)d_in[12];
    const float* v2  = (const float*)d_in[13];
    const float* W3  = (const float*)d_in[14];
    const float* b3  = (const float*)d_in[15];
    float* out = (float*)d_out;

    static bool attr_set = false;
    if (!attr_set) {
        cudaFuncSetAttribute(vfe_hmma_kernel,
                             cudaFuncAttributeMaxDynamicSharedMemorySize, SMEM_TOTAL);
        attr_set = true;
    }

    prep_kernel<<<1, 128>>>(W1, b1, g1, be1, m1, v1, W2, b2, g2, be2, m2, v2, W3,
                            (const int*)np);
    vfe_hmma_kernel<<<NTILES, 128, SMEM_TOTAL>>>(vf, np, b3, out);
}

// round 13
// speedup vs baseline: 8.5067x; 1.3776x over previous
#include <cuda_runtime.h>
#include <cuda_bf16.h>
#include <cstdint>

#define NVOX 50000
#define PPV  32
#define CIN  4
#define HID  64
#define OUT  128
#define EPSV 1e-5f

#define TILE_M 128          // rows per CTA = 4 voxels
#define NTILES (NVOX / 4)   // 12500

// ---------------- dynamic SMEM layout (bytes): B tiles only ----------------
#define OFF_B2H  0u                    // W2^T hi (64 x 64 bf16)   8KB
#define OFF_B2L  8192u                 //                          8KB
#define OFF_B3H  16384u                // W3^T hi (128 x 64 bf16) 16KB
#define OFF_B3L  32768u                //                         16KB
#define SMEM_TOTAL 49152u              // 48KB -> 3+ CTAs/SM (regs permitting)

__device__ __forceinline__ uint32_t sw128(uint32_t x) { return x ^ ((x >> 3) & 0x70); }

// ---------------- device globals (prep outputs) ----------------
__device__ __align__(16) float g_W1f[CIN * HID];
__device__ __align__(16) float g_b1f[HID];
__device__ __align__(16) float g_b2f[HID];
__device__ __align__(16) unsigned short g_B2h[HID * HID];    // [n][k] bf16, swizzled
__device__ __align__(16) unsigned short g_B2l[HID * HID];
__device__ __align__(16) unsigned short g_B3h[OUT * HID];
__device__ __align__(16) unsigned short g_B3l[OUT * HID];
__device__ int g_npts_is64;

// ---------------- PTX helpers (baseline sm_80+, no 'a' gate) ----------------
__device__ __forceinline__ uint32_t smem_u32(const void* p) {
    uint32_t a;
    asm("{ .reg .u64 t; cvta.to.shared.u64 t, %1; cvt.u32.u64 %0, t; }" : "=r"(a) : "l"(p));
    return a;
}
__device__ __forceinline__ void ldsm_x4(uint32_t* r, uint32_t addr) {
    asm volatile("ldmatrix.sync.aligned.m8n8.x4.shared.b16 {%0,%1,%2,%3}, [%4];"
                 : "=r"(r[0]), "=r"(r[1]), "=r"(r[2]), "=r"(r[3]) : "r"(addr));
}
__device__ __forceinline__ void mma_bf16(float* c, const uint32_t* a, const uint32_t* b) {
    asm volatile("mma.sync.aligned.m16n8k16.row.col.f32.bf16.bf16.f32 "
                 "{%0,%1,%2,%3}, {%4,%5,%6,%7}, {%8,%9}, {%0,%1,%2,%3};"
                 : "+f"(c[0]), "+f"(c[1]), "+f"(c[2]), "+f"(c[3])
                 : "r"(a[0]), "r"(a[1]), "r"(a[2]), "r"(a[3]), "r"(b[0]), "r"(b[1]));
}
// pack two f32 -> bf16x2 word (v0 -> low half)
__device__ __forceinline__ uint32_t pack2(float v0, float v1) {
    uint32_t r;
    asm("cvt.rn.bf16x2.f32 %0, %1, %2;" : "=r"(r) : "f"(v1), "f"(v0));
    return r;
}
// relu(c+b) -> bf16 hi + residual lo, packed
__device__ __forceinline__ void cvt_pair(float c0, float c1, float bx, float by,
                                         uint32_t& hi, uint32_t& lo) {
    float v0 = fmaxf(0.f, c0 + bx);
    float v1 = fmaxf(0.f, c1 + by);
    hi = pack2(v0, v1);
    float r0 = v0 - __uint_as_float(hi << 16);
    float r1 = v1 - __uint_as_float(hi & 0xFFFF0000u);
    lo = pack2(r0, r1);
}

// ---------------------------------------------------------------------------
// Prep kernel: BN fold, weight transpose + bf16 split + swizzle, dtype probe.
// ---------------------------------------------------------------------------
__global__ void prep_kernel(const float* __restrict__ W1, const float* __restrict__ b1,
                            const float* __restrict__ g1, const float* __restrict__ be1,
                            const float* __restrict__ m1, const float* __restrict__ v1,
                            const float* __restrict__ W2, const float* __restrict__ b2,
                            const float* __restrict__ g2, const float* __restrict__ be2,
                            const float* __restrict__ m2, const float* __restrict__ v2,
                            const float* __restrict__ W3,
                            const int* __restrict__ np32) {
    __shared__ float s2sh[HID];
    int t = threadIdx.x;
    if (t < HID) {
        float s1 = g1[t] * rsqrtf(v1[t] + EPSV);
        g_b1f[t] = (b1[t] - m1[t]) * s1 + be1[t];
#pragma unroll
        for (int c = 0; c < CIN; ++c) g_W1f[c * HID + t] = W1[c * HID + t] * s1;
        float s2 = g2[t] * rsqrtf(v2[t] + EPSV);
        g_b2f[t] = (b2[t] - m2[t]) * s2 + be2[t];
        s2sh[t] = s2;
    }
    if (t == 0) g_npts_is64 = (np32[1] == 0) ? 1 : 0;
    __syncthreads();

    // B2[n][k] = W2[k][n] * s2[n], swizzled, split hi/lo
    for (int i = t; i < HID * HID; i += blockDim.x) {
        int n = i / HID, k = i % HID;
        float v = W2[k * HID + n] * s2sh[n];
        __nv_bfloat16 bh = __float2bfloat16(v);
        float rl = v - __bfloat162float(bh);
        __nv_bfloat16 bl = __float2bfloat16(rl);
        uint32_t idx = sw128((uint32_t)(n * 128 + k * 2)) >> 1;
        g_B2h[idx] = __bfloat16_as_ushort(bh);
        g_B2l[idx] = __bfloat16_as_ushort(bl);
    }
    // B3[n][k] = W3[k][n], swizzled, split hi/lo
    for (int i = t; i < OUT * HID; i += blockDim.x) {
        int n = i / HID, k = i % HID;
        float v = W3[k * OUT + n];
        __nv_bfloat16 bh = __float2bfloat16(v);
        float rl = v - __bfloat162float(bh);
        __nv_bfloat16 bl = __float2bfloat16(rl);
        uint32_t idx = sw128((uint32_t)(n * 128 + k * 2)) >> 1;
        g_B3h[idx] = __bfloat16_as_ushort(bh);
        g_B3l[idx] = __bfloat16_as_ushort(bl);
    }
}

// ---------------------------------------------------------------------------
// Main kernel: 1 CTA = 128 rows = 4 voxels. mma.sync bf16x3 for layers 2+3.
// Warp w owns rows 32w..32w+31 == voxel blockIdx.x*4 + w.
// Layer-1 output built DIRECTLY in a-fragment registers (no A smem).
// ---------------------------------------------------------------------------
__global__ void __launch_bounds__(128, 3)
vfe_hmma_kernel(const float* __restrict__ vf,
                const void* __restrict__ npts_raw,
                const float* __restrict__ b3,
                float* __restrict__ out) {
    extern __shared__ __align__(1024) char smem[];
    const uint32_t sbase = smem_u32(smem);
    const int tid = threadIdx.x;
    const int wid = tid >> 5;
    const int lane = tid & 31;

    // ---- stage B tiles (pre-swizzled; linear uint4 copies, 48KB) ----
    {
        uint4* d; const uint4* s;
        d = (uint4*)(smem + OFF_B2H); s = (const uint4*)g_B2h;
        for (int i = tid; i < 512; i += 128) d[i] = s[i];
        d = (uint4*)(smem + OFF_B2L); s = (const uint4*)g_B2l;
        for (int i = tid; i < 512; i += 128) d[i] = s[i];
        d = (uint4*)(smem + OFF_B3H); s = (const uint4*)g_B3h;
        for (int i = tid; i < 1024; i += 128) d[i] = s[i];
        d = (uint4*)(smem + OFF_B3L); s = (const uint4*)g_B3l;
        for (int i = tid; i < 1024; i += 128) d[i] = s[i];
    }

    const int t4 = lane & 3;
    const int r0 = lane >> 2;

    // ---- layer 1 (4 -> 64) computed straight into m16k16 A fragments ----
    // lane holds rows r0+8i (i=0..3; mt=i>>1) and cols 16ks+2t4+8cp+{0,1}
    uint32_t ahi[2][4][4], alo[2][4][4];   // [mt][ks][reg]
    {
        float4 xr[4];
#pragma unroll
        for (int i = 0; i < 4; ++i)
            xr[i] = ((const float4*)vf)[blockIdx.x * TILE_M + wid * 32 + r0 + 8 * i];
#pragma unroll
        for (int ks = 0; ks < 4; ++ks) {
#pragma unroll
            for (int cp = 0; cp < 2; ++cp) {
                const int c = 16 * ks + 2 * t4 + 8 * cp;
                const float2 bb = *(const float2*)(g_b1f + c);
                const float2 w0 = *(const float2*)(g_W1f + 0 * HID + c);
                const float2 w1 = *(const float2*)(g_W1f + 1 * HID + c);
                const float2 w2 = *(const float2*)(g_W1f + 2 * HID + c);
                const float2 w3 = *(const float2*)(g_W1f + 3 * HID + c);
#pragma unroll
                for (int i = 0; i < 4; ++i) {
                    const float4 x = xr[i];
                    float v0 = fmaxf(0.f, bb.x + x.x * w0.x + x.y * w1.x + x.z * w2.x + x.w * w3.x);
                    float v1 = fmaxf(0.f, bb.y + x.x * w0.y + x.y * w1.y + x.z * w2.y + x.w * w3.y);
                    uint32_t hi = pack2(v0, v1);
                    float rr0 = v0 - __uint_as_float(hi << 16);
                    float rr1 = v1 - __uint_as_float(hi & 0xFFFF0000u);
                    ahi[i >> 1][ks][(i & 1) + 2 * cp] = hi;
                    alo[i >> 1][ks][(i & 1) + 2 * cp] = pack2(rr0, rr1);
                }
            }
        }
    }
    __syncthreads();   // B tiles staged

    // ---- B ldmatrix addressing (x4 = two n-tiles per load) ----
    const uint32_t swz = (uint32_t)(lane & 7) << 4;
    const uint32_t bRow = (uint32_t)(lane & 7) + (uint32_t)((lane >> 4) << 3);  // + n-tile pair sel
    const uint32_t bColSel = (uint32_t)((lane & 8) << 1);

    // ---- layer 2: acc2[mt][nt][4] = A(128x64) @ B2^T, bf16x3 ----
    float acc2[2][8][4];
#pragma unroll
    for (int mt = 0; mt < 2; ++mt)
#pragma unroll
        for (int nt = 0; nt < 8; ++nt)
#pragma unroll
            for (int q = 0; q < 4; ++q) acc2[mt][nt][q] = 0.f;

#pragma unroll
    for (int ks = 0; ks < 4; ++ks) {    // round 1: Bh with BOTH ahi and alo
        const uint32_t colB = (32u * ks + bColSel) ^ swz;
        uint32_t bf[4][4];
#pragma unroll
        for (int p = 0; p < 4; ++p)
            ldsm_x4(bf[p], sbase + OFF_B2H + (16u * p + bRow) * 128u + colB);
#pragma unroll
        for (int mt = 0; mt < 2; ++mt)
#pragma unroll
            for (int p = 0; p < 4; ++p) {
                mma_bf16(acc2[mt][2 * p],     ahi[mt][ks], &bf[p][0]);
                mma_bf16(acc2[mt][2 * p + 1], ahi[mt][ks], &bf[p][2]);
                mma_bf16(acc2[mt][2 * p],     alo[mt][ks], &bf[p][0]);
                mma_bf16(acc2[mt][2 * p + 1], alo[mt][ks], &bf[p][2]);
            }
    }
#pragma unroll
    for (int ks = 0; ks < 4; ++ks) {    // round 2: Bl with ahi only
        const uint32_t colB = (32u * ks + bColSel) ^ swz;
        uint32_t bf[4][4];
#pragma unroll
        for (int p = 0; p < 4; ++p)
            ldsm_x4(bf[p], sbase + OFF_B2L + (16u * p + bRow) * 128u + colB);
#pragma unroll
        for (int mt = 0; mt < 2; ++mt)
#pragma unroll
            for (int p = 0; p < 4; ++p) {
                mma_bf16(acc2[mt][2 * p],     ahi[mt][ks], &bf[p][0]);
                mma_bf16(acc2[mt][2 * p + 1], ahi[mt][ks], &bf[p][2]);
            }
    }

    // ---- convert: relu(acc2+b2) -> layer-3 A fragments (in-place reuse) ----
    // acc(m16n16 from n-tile pair) layout == a-frag(m16k16) layout.
#pragma unroll
    for (int ks = 0; ks < 4; ++ks) {
        const int nt0 = 2 * ks, nt1 = 2 * ks + 1;
        const float2 bb0 = *(const float2*)(g_b2f + 8 * nt0 + 2 * t4);
        const float2 bb1 = *(const float2*)(g_b2f + 8 * nt1 + 2 * t4);
#pragma unroll
        for (int mt = 0; mt < 2; ++mt) {
            cvt_pair(acc2[mt][nt0][0], acc2[mt][nt0][1], bb0.x, bb0.y, ahi[mt][ks][0], alo[mt][ks][0]);
            cvt_pair(acc2[mt][nt0][2], acc2[mt][nt0][3], bb0.x, bb0.y, ahi[mt][ks][1], alo[mt][ks][1]);
            cvt_pair(acc2[mt][nt1][0], acc2[mt][nt1][1], bb1.x, bb1.y, ahi[mt][ks][2], alo[mt][ks][2]);
            cvt_pair(acc2[mt][nt1][2], acc2[mt][nt1][3], bb1.x, bb1.y, ahi[mt][ks][3], alo[mt][ks][3]);
        }
    }

    // ---- voxel point count (for masked max) ----
    const int voxel = blockIdx.x * 4 + wid;
    int n;
    if (g_npts_is64) n = (int)((const long long*)npts_raw)[voxel];
    else             n = ((const int*)npts_raw)[voxel];
    const bool v0r = (r0      < n);
    const bool v1r = (r0 +  8 < n);
    const bool v2r = (r0 + 16 < n);
    const bool v3r = (r0 + 24 < n);
    const float NEG_INF = __int_as_float(0xff800000);

    // ---- layer 3 in four 32-col quarters + fused epilogue ----
#pragma unroll
    for (int q = 0; q < 4; ++q) {
        float acc3[2][4][4];
#pragma unroll
        for (int mt = 0; mt < 2; ++mt)
#pragma unroll
            for (int nt = 0; nt < 4; ++nt)
#pragma unroll
                for (int z = 0; z < 4; ++z) acc3[mt][nt][z] = 0.f;

        const uint32_t rowQ = (uint32_t)(32 * q);
#pragma unroll
        for (int ks = 0; ks < 4; ++ks) {    // round 1: Bh with ahi + alo
            const uint32_t colB = (32u * ks + bColSel) ^ swz;
            uint32_t bf[2][4];
#pragma unroll
            for (int p = 0; p < 2; ++p)
                ldsm_x4(bf[p], sbase + OFF_B3H + (rowQ + 16u * p + bRow) * 128u + colB);
#pragma unroll
            for (int mt = 0; mt < 2; ++mt)
#pragma unroll
                for (int p = 0; p < 2; ++p) {
                    mma_bf16(acc3[mt][2 * p],     ahi[mt][ks], &bf[p][0]);
                    mma_bf16(acc3[mt][2 * p + 1], ahi[mt][ks], &bf[p][2]);
                    mma_bf16(acc3[mt][2 * p],     alo[mt][ks], &bf[p][0]);
                    mma_bf16(acc3[mt][2 * p + 1], alo[mt][ks], &bf[p][2]);
                }
        }
#pragma unroll
        for (int ks = 0; ks < 4; ++ks) {    // round 2: Bl with ahi only
            const uint32_t colB = (32u * ks + bColSel) ^ swz;
            uint32_t bf[2][4];
#pragma unroll
            for (int p = 0; p < 2; ++p)
                ldsm_x4(bf[p], sbase + OFF_B3L + (rowQ + 16u * p + bRow) * 128u + colB);
#pragma unroll
            for (int mt = 0; mt < 2; ++mt)
#pragma unroll
                for (int p = 0; p < 2; ++p) {
                    mma_bf16(acc3[mt][2 * p],     ahi[mt][ks], &bf[p][0]);
                    mma_bf16(acc3[mt][2 * p + 1], ahi[mt][ks], &bf[p][2]);
                }
        }

        // epilogue: masked max over 32 rows (points), +b3 after max
#pragma unroll
        for (int nt = 0; nt < 4; ++nt) {
            float m0 = v0r ? acc3[0][nt][0] : NEG_INF;
            float m1 = v0r ? acc3[0][nt][1] : NEG_INF;
            m0 = fmaxf(m0, v1r ? acc3[0][nt][2] : NEG_INF);
            m1 = fmaxf(m1, v1r ? acc3[0][nt][3] : NEG_INF);
            m0 = fmaxf(m0, v2r ? acc3[1][nt][0] : NEG_INF);
            m1 = fmaxf(m1, v2r ? acc3[1][nt][1] : NEG_INF);
            m0 = fmaxf(m0, v3r ? acc3[1][nt][2] : NEG_INF);
            m1 = fmaxf(m1, v3r ? acc3[1][nt][3] : NEG_INF);
#pragma unroll
            for (int d = 4; d <= 16; d <<= 1) {
                m0 = fmaxf(m0, __shfl_xor_sync(0xffffffffu, m0, d));
                m1 = fmaxf(m1, __shfl_xor_sync(0xffffffffu, m1, d));
            }
            if (lane < 4) {
                const int col = 32 * q + 8 * nt + 2 * lane;
                const float2 bb = *(const float2*)(b3 + col);
                *(float2*)(out + (size_t)voxel * OUT + col) = make_float2(m0 + bb.x, m1 + bb.y);
            }
        }
    }
}

// ---------------------------------------------------------------------------
// Launch
// ---------------------------------------------------------------------------
extern "C" void kernel_launch(void* const* d_in, const int* in_sizes, int n_in,
                              void* d_out, int out_size) {
    const float* vf  = (const float*)d_in[0];
    const void*  np  = d_in[1];
    const float* W1  = (const float*)d_in[2];
    const float* b1  = (const float*)d_in[3];
    const float* g1  = (const float*)d_in[4];
    const float* be1 = (const float*)d_in[5];
    const float* m1  = (const float*)d_in[6];
    const float* v1  = (const float*)d_in[7];
    const float* W2  = (const float*)d_in[8];
    const float* b2  = (const float*)d_in[9];
    const float* g2  = (const float*)d_in[10];
    const float* be2 = (const float*)d_in[11];
    const float* m2  = (const float*)d_in[12];
    const float* v2  = (const float*)d_in[13];
    const float* W3  = (const float*)d_in[14];
    const float* b3  = (const float*)d_in[15];
    float* out = (float*)d_out;

    static bool attr_set = false;
    if (!attr_set) {
        cudaFuncSetAttribute(vfe_hmma_kernel,
                             cudaFuncAttributeMaxDynamicSharedMemorySize, SMEM_TOTAL);
        attr_set = true;
    }

    prep_kernel<<<1, 128>>>(W1, b1, g1, be1, m1, v1, W2, b2, g2, be2, m2, v2, W3,
                            (const int*)np);
    vfe_hmma_kernel<<<NTILES, 128, SMEM_TOTAL>>>(vf, np, b3, out);
}

// round 15
// speedup vs baseline: 17.0442x; 2.0036x over previous
#include <cuda_runtime.h>
#include <cuda_fp16.h>
#include <cstdint>

#define NVOX 50000
#define PPV  32
#define CIN  4
#define HID  64
#define OUT  128
#define EPSV 1e-5f

#define TILE_M 128          // rows per CTA = 4 voxels
#define NTILES (NVOX / 4)   // 12500

// ---------------- dynamic SMEM layout (bytes): fp16 B tiles only ----------------
#define OFF_B2   0u                    // W2^T fp16 (64 x 64)   8KB
#define OFF_B3   8192u                 // W3^T fp16 (128 x 64) 16KB
#define SMEM_TOTAL 24576u              // 24KB -> smem allows 8 CTAs/SM

__device__ __forceinline__ uint32_t sw128(uint32_t x) { return x ^ ((x >> 3) & 0x70); }

// ---------------- device globals (prep outputs) ----------------
__device__ __align__(16) float g_W1f[CIN * HID];
__device__ __align__(16) float g_b1f[HID];
__device__ __align__(16) float g_b2f[HID];
__device__ __align__(16) unsigned short g_B2[HID * HID];    // [n][k] fp16, swizzled
__device__ __align__(16) unsigned short g_B3[OUT * HID];
__device__ int g_npts_is64;

// ---------------- PTX helpers (baseline sm_80+, no 'a' gate) ----------------
__device__ __forceinline__ uint32_t smem_u32(const void* p) {
    uint32_t a;
    asm("{ .reg .u64 t; cvta.to.shared.u64 t, %1; cvt.u32.u64 %0, t; }" : "=r"(a) : "l"(p));
    return a;
}
__device__ __forceinline__ void ldsm_x4(uint32_t* r, uint32_t addr) {
    asm volatile("ldmatrix.sync.aligned.m8n8.x4.shared.b16 {%0,%1,%2,%3}, [%4];"
                 : "=r"(r[0]), "=r"(r[1]), "=r"(r[2]), "=r"(r[3]) : "r"(addr));
}
__device__ __forceinline__ void mma_f16(float* c, const uint32_t* a, const uint32_t* b) {
    asm volatile("mma.sync.aligned.m16n8k16.row.col.f32.f16.f16.f32 "
                 "{%0,%1,%2,%3}, {%4,%5,%6,%7}, {%8,%9}, {%0,%1,%2,%3};"
                 : "+f"(c[0]), "+f"(c[1]), "+f"(c[2]), "+f"(c[3])
                 : "r"(a[0]), "r"(a[1]), "r"(a[2]), "r"(a[3]), "r"(b[0]), "r"(b[1]));
}
// pack two f32 -> f16x2 word (v0 -> low half)
__device__ __forceinline__ uint32_t pack2h(float v0, float v1) {
    uint32_t r;
    asm("cvt.rn.f16x2.f32 %0, %1, %2;" : "=r"(r) : "f"(v1), "f"(v0));
    return r;
}

// ---------------------------------------------------------------------------
// Prep kernel: BN fold, weight transpose + fp16 convert + swizzle, dtype probe.
// ---------------------------------------------------------------------------
__global__ void prep_kernel(const float* __restrict__ W1, const float* __restrict__ b1,
                            const float* __restrict__ g1, const float* __restrict__ be1,
                            const float* __restrict__ m1, const float* __restrict__ v1,
                            const float* __restrict__ W2, const float* __restrict__ b2,
                            const float* __restrict__ g2, const float* __restrict__ be2,
                            const float* __restrict__ m2, const float* __restrict__ v2,
                            const float* __restrict__ W3,
                            const int* __restrict__ np32) {
    __shared__ float s2sh[HID];
    int t = threadIdx.x;
    if (t < HID) {
        float s1 = g1[t] * rsqrtf(v1[t] + EPSV);
        g_b1f[t] = (b1[t] - m1[t]) * s1 + be1[t];
#pragma unroll
        for (int c = 0; c < CIN; ++c) g_W1f[c * HID + t] = W1[c * HID + t] * s1;
        float s2 = g2[t] * rsqrtf(v2[t] + EPSV);
        g_b2f[t] = (b2[t] - m2[t]) * s2 + be2[t];
        s2sh[t] = s2;
    }
    if (t == 0) g_npts_is64 = (np32[1] == 0) ? 1 : 0;
    __syncthreads();

    // B2[n][k] = W2[k][n] * s2[n], fp16, swizzled
    for (int i = t; i < HID * HID; i += blockDim.x) {
        int n = i / HID, k = i % HID;
        float v = W2[k * HID + n] * s2sh[n];
        uint32_t idx = sw128((uint32_t)(n * 128 + k * 2)) >> 1;
        g_B2[idx] = __half_as_ushort(__float2half_rn(v));
    }
    // B3[n][k] = W3[k][n], fp16, swizzled
    for (int i = t; i < OUT * HID; i += blockDim.x) {
        int n = i / HID, k = i % HID;
        float v = W3[k * OUT + n];
        uint32_t idx = sw128((uint32_t)(n * 128 + k * 2)) >> 1;
        g_B3[idx] = __half_as_ushort(__float2half_rn(v));
    }
}

// ---------------------------------------------------------------------------
// Main kernel: 1 CTA = 128 rows = 4 voxels. Single-pass fp16 mma for layers 2+3.
// Warp w owns rows 32w..32w+31 == voxel blockIdx.x*4 + w.
// ---------------------------------------------------------------------------
__global__ void __launch_bounds__(128, 4)
vfe_hmma_kernel(const float* __restrict__ vf,
                const void* __restrict__ npts_raw,
                const float* __restrict__ b3,
                float* __restrict__ out) {
    extern __shared__ __align__(1024) char smem[];
    const uint32_t sbase = smem_u32(smem);
    const int tid = threadIdx.x;
    const int wid = tid >> 5;
    const int lane = tid & 31;

    // ---- stage B tiles (pre-swizzled; linear uint4 copies, 24KB) ----
    {
        uint4* d; const uint4* s;
        d = (uint4*)(smem + OFF_B2); s = (const uint4*)g_B2;
        for (int i = tid; i < 512; i += 128) d[i] = s[i];
        d = (uint4*)(smem + OFF_B3); s = (const uint4*)g_B3;
        for (int i = tid; i < 1024; i += 128) d[i] = s[i];
    }

    const int t4 = lane & 3;
    const int r0 = lane >> 2;

    // ---- layer 1 (4 -> 64) computed straight into m16k16 fp16 A fragments ----
    // lane holds rows r0+8i (i=0..3; mt=i>>1) and cols 16ks+2t4+8cp+{0,1}
    uint32_t af[2][4][4];   // [mt][ks][reg]
    {
        float4 xr[4];
#pragma unroll
        for (int i = 0; i < 4; ++i)
            xr[i] = ((const float4*)vf)[blockIdx.x * TILE_M + wid * 32 + r0 + 8 * i];
#pragma unroll
        for (int ks = 0; ks < 4; ++ks) {
#pragma unroll
            for (int cp = 0; cp < 2; ++cp) {
                const int c = 16 * ks + 2 * t4 + 8 * cp;
                const float2 bb = *(const float2*)(g_b1f + c);
                const float2 w0 = *(const float2*)(g_W1f + 0 * HID + c);
                const float2 w1 = *(const float2*)(g_W1f + 1 * HID + c);
                const float2 w2 = *(const float2*)(g_W1f + 2 * HID + c);
                const float2 w3 = *(const float2*)(g_W1f + 3 * HID + c);
#pragma unroll
                for (int i = 0; i < 4; ++i) {
                    const float4 x = xr[i];
                    float v0 = fmaxf(0.f, bb.x + x.x * w0.x + x.y * w1.x + x.z * w2.x + x.w * w3.x);
                    float v1 = fmaxf(0.f, bb.y + x.x * w0.y + x.y * w1.y + x.z * w2.y + x.w * w3.y);
                    af[i >> 1][ks][(i & 1) + 2 * cp] = pack2h(v0, v1);
                }
            }
        }
    }
    __syncthreads();   // B tiles staged

    // ---- B ldmatrix addressing (x4 = two n-tiles per load) ----
    const uint32_t swz = (uint32_t)(lane & 7) << 4;
    const uint32_t bRow = (uint32_t)(lane & 7) + (uint32_t)((lane >> 4) << 3);
    const uint32_t bColSel = (uint32_t)((lane & 8) << 1);

    // ---- layer 2: acc2[mt][nt][4] = A(128x64) @ B2^T, single-pass fp16 ----
    float acc2[2][8][4];
#pragma unroll
    for (int mt = 0; mt < 2; ++mt)
#pragma unroll
        for (int nt = 0; nt < 8; ++nt)
#pragma unroll
            for (int q = 0; q < 4; ++q) acc2[mt][nt][q] = 0.f;

#pragma unroll
    for (int ks = 0; ks < 4; ++ks) {
        const uint32_t colB = (32u * ks + bColSel) ^ swz;
        uint32_t bf[4][4];
#pragma unroll
        for (int p = 0; p < 4; ++p)
            ldsm_x4(bf[p], sbase + OFF_B2 + (16u * p + bRow) * 128u + colB);
#pragma unroll
        for (int mt = 0; mt < 2; ++mt)
#pragma unroll
            for (int p = 0; p < 4; ++p) {
                mma_f16(acc2[mt][2 * p],     af[mt][ks], &bf[p][0]);
                mma_f16(acc2[mt][2 * p + 1], af[mt][ks], &bf[p][2]);
            }
    }

    // ---- convert: relu(acc2+b2) -> layer-3 fp16 A fragments (overwrite af) ----
    // acc(m16n16 from n-tile pair) layout == a-frag(m16k16) layout.
#pragma unroll
    for (int ks = 0; ks < 4; ++ks) {
        const int nt0 = 2 * ks, nt1 = 2 * ks + 1;
        const float2 bb0 = *(const float2*)(g_b2f + 8 * nt0 + 2 * t4);
        const float2 bb1 = *(const float2*)(g_b2f + 8 * nt1 + 2 * t4);
#pragma unroll
        for (int mt = 0; mt < 2; ++mt) {
            af[mt][ks][0] = pack2h(fmaxf(0.f, acc2[mt][nt0][0] + bb0.x),
                                   fmaxf(0.f, acc2[mt][nt0][1] + bb0.y));
            af[mt][ks][1] = pack2h(fmaxf(0.f, acc2[mt][nt0][2] + bb0.x),
                                   fmaxf(0.f, acc2[mt][nt0][3] + bb0.y));
            af[mt][ks][2] = pack2h(fmaxf(0.f, acc2[mt][nt1][0] + bb1.x),
                                   fmaxf(0.f, acc2[mt][nt1][1] + bb1.y));
            af[mt][ks][3] = pack2h(fmaxf(0.f, acc2[mt][nt1][2] + bb1.x),
                                   fmaxf(0.f, acc2[mt][nt1][3] + bb1.y));
        }
    }

    // ---- voxel point count (for masked max) ----
    const int voxel = blockIdx.x * 4 + wid;
    int n;
    if (g_npts_is64) n = (int)((const long long*)npts_raw)[voxel];
    else             n = ((const int*)npts_raw)[voxel];
    const bool v0r = (r0      < n);
    const bool v1r = (r0 +  8 < n);
    const bool v2r = (r0 + 16 < n);
    const bool v3r = (r0 + 24 < n);
    const float NEG_INF = __int_as_float(0xff800000);

    // ---- layer 3 in four 32-col quarters + fused epilogue, single-pass fp16 ----
#pragma unroll
    for (int q = 0; q < 4; ++q) {
        float acc3[2][4][4];
#pragma unroll
        for (int mt = 0; mt < 2; ++mt)
#pragma unroll
            for (int nt = 0; nt < 4; ++nt)
#pragma unroll
                for (int z = 0; z < 4; ++z) acc3[mt][nt][z] = 0.f;

        const uint32_t rowQ = (uint32_t)(32 * q);
#pragma unroll
        for (int ks = 0; ks < 4; ++ks) {
            const uint32_t colB = (32u * ks + bColSel) ^ swz;
            uint32_t bf[2][4];
#pragma unroll
            for (int p = 0; p < 2; ++p)
                ldsm_x4(bf[p], sbase + OFF_B3 + (rowQ + 16u * p + bRow) * 128u + colB);
#pragma unroll
            for (int mt = 0; mt < 2; ++mt)
#pragma unroll
                for (int p = 0; p < 2; ++p) {
                    mma_f16(acc3[mt][2 * p],     af[mt][ks], &bf[p][0]);
                    mma_f16(acc3[mt][2 * p + 1], af[mt][ks], &bf[p][2]);
                }
        }

        // epilogue: masked max over 32 rows (points), +b3 after max
#pragma unroll
        for (int nt = 0; nt < 4; ++nt) {
            float m0 = v0r ? acc3[0][nt][0] : NEG_INF;
            float m1 = v0r ? acc3[0][nt][1] : NEG_INF;
            m0 = fmaxf(m0, v1r ? acc3[0][nt][2] : NEG_INF);
            m1 = fmaxf(m1, v1r ? acc3[0][nt][3] : NEG_INF);
            m0 = fmaxf(m0, v2r ? acc3[1][nt][0] : NEG_INF);
            m1 = fmaxf(m1, v2r ? acc3[1][nt][1] : NEG_INF);
            m0 = fmaxf(m0, v3r ? acc3[1][nt][2] : NEG_INF);
            m1 = fmaxf(m1, v3r ? acc3[1][nt][3] : NEG_INF);
#pragma unroll
            for (int d = 4; d <= 16; d <<= 1) {
                m0 = fmaxf(m0, __shfl_xor_sync(0xffffffffu, m0, d));
                m1 = fmaxf(m1, __shfl_xor_sync(0xffffffffu, m1, d));
            }
            if (lane < 4) {
                const int col = 32 * q + 8 * nt + 2 * lane;
                const float2 bb = *(const float2*)(b3 + col);
                *(float2*)(out + (size_t)voxel * OUT + col) = make_float2(m0 + bb.x, m1 + bb.y);
            }
        }
    }
}

// ---------------------------------------------------------------------------
// Launch
// ---------------------------------------------------------------------------
extern "C" void kernel_launch(void* const* d_in, const int* in_sizes, int n_in,
                              void* d_out, int out_size) {
    const float* vf  = (const float*)d_in[0];
    const void*  np  = d_in[1];
    const float* W1  = (const float*)d_in[2];
    const float* b1  = (const float*)d_in[3];
    const float* g1  = (const float*)d_in[4];
    const float* be1 = (const float*)d_in[5];
    const float* m1  = (const float*)d_in[6];
    const float* v1  = (const float*)d_in[7];
    const float* W2  = (const float*)d_in[8];
    const float* b2  = (const float*)d_in[9];
    const float* g2  = (const float*)d_in[10];
    const float* be2 = (const float*)d_in[11];
    const float* m2  = (const float*)d_in[12];
    const float* v2  = (const float*)d_in[13];
    const float* W3  = (const float*)d_in[14];
    const float* b3  = (const float*)d_in[15];
    float* out = (float*)d_out;

    prep_kernel<<<1, 128>>>(W1, b1, g1, be1, m1, v1, W2, b2, g2, be2, m2, v2, W3,
                            (const int*)np);
    vfe_hmma_kernel<<<NTILES, 128, SMEM_TOTAL>>>(vf, np, b3, out);
}